// round 15
// baseline (speedup 1.0000x reference)
#include <cuda_runtime.h>
#include <cuda_bf16.h>
#include <cstdint>

// ---------------------------------------------------------------------------
// Stein solver, low-rank factored truncated series, row-form factor chains.
//   S_N = sum_{j<N} M^j R A^j,  M = A_F^T,  R = C_F^T Cm (rank 512).
//   Ut_{j+1} = Ut_j @ M^T (Bt = M),  V_{j+1} = V_j @ A (Bt = At).
// Truncation at t5 (validated R7-R14).
// Chain steps now run through the PROVEN gemm_g shape (128x128 CTA tile,
// 128 thr, warp 64x64, KCH=16, 4-stage, stride-24) as a dual kernel with
// grid (16, 4, 2) = 128 CTAs -- the only shape measured near HMMA peak.
// Final: one mixed-precision GEMM over K=2560 (k<1024 3-split, rest 1-split).
// ---------------------------------------------------------------------------

#define NDIM 2048
#define PDIM 512
#define FULL ((size_t)NDIM * NDIM)
#define SL   ((size_t)PDIM * NDIM)          /* one 512x2048 slice */
#define KC3  2560                           /* concat K = 5 * 512 */

// Us(5SL) Vs(5SL) Uc(5SL) Vc(5SL) M(4SL) At(4SL)
__device__ float g_buf[(size_t)28 * SL];

// ---------------------------------------------------------------------------
__device__ __forceinline__ uint32_t smem_u32(const void* p) {
    uint32_t a;
    asm("{ .reg .u64 t; cvta.to.shared.u64 t, %1; cvt.u32.u64 %0, t; }"
        : "=r"(a) : "l"(p));
    return a;
}

__device__ __forceinline__ void cp16(uint32_t saddr, const void* g) {
    asm volatile("cp.async.cg.shared.global [%0], [%1], 16;"
                 :: "r"(saddr), "l"(g));
}

__device__ __forceinline__ void cp_commit() {
    asm volatile("cp.async.commit_group;");
}

template <int N>
__device__ __forceinline__ void cp_wait() {
    asm volatile("cp.async.wait_group %0;" :: "n"(N));
}

__device__ __forceinline__ void split3(float f0, float f1,
                                       uint32_t& hi, uint32_t& lo) {
    uint32_t u0 = __float_as_uint(f0) & 0xffff0000u;
    uint32_t u1 = __float_as_uint(f1) & 0xffff0000u;
    hi = u1 | (u0 >> 16);
    float r0 = f0 - __uint_as_float(u0);
    float r1 = f1 - __uint_as_float(u1);
    asm("cvt.rn.bf16x2.f32 %0, %1, %2;" : "=r"(lo) : "f"(r1), "f"(r0));
}

__device__ __forceinline__ uint32_t pack1(float f0, float f1) {
    uint32_t r;
    asm("cvt.rn.bf16x2.f32 %0, %1, %2;" : "=r"(r) : "f"(f1), "f"(f0));
    return r;
}

__device__ __forceinline__ void mma_bf16(float* d, const uint32_t* a,
                                         const uint32_t* b) {
    asm volatile(
        "mma.sync.aligned.m16n8k16.row.col.f32.bf16.bf16.f32 "
        "{%0,%1,%2,%3}, {%4,%5,%6,%7}, {%8,%9}, {%0,%1,%2,%3};"
        : "+f"(d[0]), "+f"(d[1]), "+f"(d[2]), "+f"(d[3])
        : "r"(a[0]), "r"(a[1]), "r"(a[2]), "r"(a[3]), "r"(b[0]), "r"(b[1]));
}

// ---------------------------------------------------------------------------
// Dual transpose: dst[c*ldd + r] = src[r*lds + c], z selects pair.
// ---------------------------------------------------------------------------
__global__ void transpose_g(const float* __restrict__ s0, float* __restrict__ d0,
                            const float* __restrict__ s1, float* __restrict__ d1,
                            int R, int C, int lds, int ldd)
{
    const float* src = blockIdx.z ? s1 : s0;
    float* dst = blockIdx.z ? d1 : d0;
    __shared__ float tile[32][33];
    int x = blockIdx.x * 32 + threadIdx.x;
    int y = blockIdx.y * 32 + threadIdx.y;
    #pragma unroll
    for (int i = 0; i < 32; i += 8)
        if (y + i < R && x < C)
            tile[threadIdx.y + i][threadIdx.x] = src[(size_t)(y + i) * lds + x];
    __syncthreads();
    x = blockIdx.y * 32 + threadIdx.x;
    y = blockIdx.x * 32 + threadIdx.y;
    #pragma unroll
    for (int i = 0; i < 32; i += 8)
        if (y + i < C && x < R)
            dst[(size_t)(y + i) * ldd + x] = tile[threadIdx.x][threadIdx.y + i];
}

// ---------------------------------------------------------------------------
// Dual GEMM, gemm_g shape (proven at peak): C = A @ Bt^T, z selects operands.
// CTA 128x128, 128 thr (4 warps 2x2, warp 64x64), KCH=16, 4-stage pipeline,
// stride-24 rows, 2 CTAs/SM. Used for chain steps with grid (16, My, 2).
// ---------------------------------------------------------------------------
#define KCH 16
#define ROWSTRIDE 24
#define STAGES 4
#define PLANE_FLOATS (128 * ROWSTRIDE)
#define STAGE_FLOATS (2 * PLANE_FLOATS)
#define SMEM_DYN (STAGES * STAGE_FLOATS * 4)

template <int NSPLIT>
__global__ void __launch_bounds__(128, 2)
gemm_gd(const float* __restrict__ A0, const float* __restrict__ B0,
        float* __restrict__ C0,
        const float* __restrict__ A1, const float* __restrict__ B1,
        float* __restrict__ C1, int K)
{
    extern __shared__ float sm[];

    const float* A = blockIdx.z ? A1 : A0;
    const float* Bt = blockIdx.z ? B1 : B0;
    float* C = blockIdx.z ? C1 : C0;

    const int tid  = threadIdx.x;
    const int wid  = tid >> 5;
    const int lane = tid & 31;
    const int grp  = lane >> 2;
    const int qk   = lane & 3;

    const int bx = blockIdx.x;
    const int by = blockIdx.y;
    const int wm = (wid >> 1) * 64;
    const int wn = (wid & 1) * 64;

    const float* Ab = A  + (size_t)(by * 128) * K;
    const float* Bb = Bt + (size_t)(bx * 128) * K;

    const int crow = tid >> 2;
    const int ckg  = (tid & 3) * 4;

    auto issue = [&](int ct, int slot) {
        float* sA = sm + slot * STAGE_FLOATS;
        float* sB = sA + PLANE_FLOATS;
        const int k0 = ct * KCH;
        #pragma unroll
        for (int p = 0; p < 4; p++) {
            const int r = crow + p * 32;
            const uint32_t so = (uint32_t)(r * ROWSTRIDE + ckg);
            cp16(smem_u32(sA + so), Ab + (size_t)r * K + k0 + ckg);
            cp16(smem_u32(sB + so), Bb + (size_t)r * K + k0 + ckg);
        }
        cp_commit();
    };

    float acc[4][8][4];
    #pragma unroll
    for (int i = 0; i < 4; i++)
        #pragma unroll
        for (int j = 0; j < 8; j++)
            #pragma unroll
            for (int q = 0; q < 4; q++)
                acc[i][j][q] = 0.f;

    const int NC = K / KCH;

    #pragma unroll
    for (int s = 0; s < STAGES - 1; s++) issue(s, s);

    for (int ct = 0; ct < NC; ct++) {
        cp_wait<STAGES - 2>();
        __syncthreads();

        if (ct + STAGES - 1 < NC)
            issue(ct + STAGES - 1, (ct + STAGES - 1) & (STAGES - 1));

        const float* sA = sm + (ct & (STAGES - 1)) * STAGE_FLOATS;
        const float* sB = sA + PLANE_FLOATS;

        uint32_t bh[8][2], bl[8][2];
        #pragma unroll
        for (int j = 0; j < 8; j++) {
            const int n = wn + j * 8 + grp;
            float2 q0 = *(const float2*)&sB[n * ROWSTRIDE + 2 * qk];
            float2 q1 = *(const float2*)&sB[n * ROWSTRIDE + 2 * qk + 8];
            if (NSPLIT == 3) {
                split3(q0.x, q0.y, bh[j][0], bl[j][0]);
                split3(q1.x, q1.y, bh[j][1], bl[j][1]);
            } else {
                bh[j][0] = pack1(q0.x, q0.y);
                bh[j][1] = pack1(q1.x, q1.y);
            }
        }
        #pragma unroll
        for (int i = 0; i < 4; i++) {
            const int r = wm + i * 16 + grp;
            float2 a0 = *(const float2*)&sA[r * ROWSTRIDE + 2 * qk];
            float2 a1 = *(const float2*)&sA[(r + 8) * ROWSTRIDE + 2 * qk];
            float2 a2 = *(const float2*)&sA[r * ROWSTRIDE + 2 * qk + 8];
            float2 a3 = *(const float2*)&sA[(r + 8) * ROWSTRIDE + 2 * qk + 8];
            uint32_t ah[4], al[4];
            if (NSPLIT == 3) {
                split3(a0.x, a0.y, ah[0], al[0]);
                split3(a1.x, a1.y, ah[1], al[1]);
                split3(a2.x, a2.y, ah[2], al[2]);
                split3(a3.x, a3.y, ah[3], al[3]);
            } else {
                ah[0] = pack1(a0.x, a0.y);
                ah[1] = pack1(a1.x, a1.y);
                ah[2] = pack1(a2.x, a2.y);
                ah[3] = pack1(a3.x, a3.y);
            }
            #pragma unroll
            for (int j = 0; j < 8; j++) mma_bf16(acc[i][j], ah, bh[j]);
            if (NSPLIT == 3) {
                #pragma unroll
                for (int j = 0; j < 8; j++) mma_bf16(acc[i][j], ah, bl[j]);
                #pragma unroll
                for (int j = 0; j < 8; j++) mma_bf16(acc[i][j], al, bh[j]);
            }
        }
    }

    #pragma unroll
    for (int i = 0; i < 4; i++) {
        const int r = by * 128 + wm + i * 16 + grp;
        #pragma unroll
        for (int j = 0; j < 8; j++) {
            const int c = bx * 128 + wn + j * 8 + qk * 2;
            size_t p0 = (size_t)r * NDIM + c;
            size_t p1 = (size_t)(r + 8) * NDIM + c;
            float2 o0 = { acc[i][j][0], acc[i][j][1] };
            float2 o1 = { acc[i][j][2], acc[i][j][3] };
            *(float2*)(C + p0) = o0;
            *(float2*)(C + p1) = o1;
        }
    }
}

// ---------------------------------------------------------------------------
// Final GEMM (gemm_f): out = Uc(2048 x 2560) @ Vc^T, mixed precision
// (k < 1024: 3-split; rest: 1-split). Same proven shape. (R13/R14 verified.)
// ---------------------------------------------------------------------------
#define SPLIT_CHUNKS (1024 / KCH)

__global__ void __launch_bounds__(128, 2)
gemm_f(const float* __restrict__ A, const float* __restrict__ Bt,
       float* __restrict__ C, int K, int lda, int ldb, int ldc)
{
    extern __shared__ float sm[];

    const int tid  = threadIdx.x;
    const int wid  = tid >> 5;
    const int lane = tid & 31;
    const int grp  = lane >> 2;
    const int qk   = lane & 3;

    const int bx = blockIdx.x;
    const int by = blockIdx.y;
    const int wm = (wid >> 1) * 64;
    const int wn = (wid & 1) * 64;

    const float* Ab = A  + (size_t)(by * 128) * lda;
    const float* Bb = Bt + (size_t)(bx * 128) * ldb;

    const int crow = tid >> 2;
    const int ckg  = (tid & 3) * 4;

    auto issue = [&](int ct, int slot) {
        float* sA = sm + slot * STAGE_FLOATS;
        float* sB = sA + PLANE_FLOATS;
        const int k0 = ct * KCH;
        #pragma unroll
        for (int p = 0; p < 4; p++) {
            const int r = crow + p * 32;
            const uint32_t so = (uint32_t)(r * ROWSTRIDE + ckg);
            cp16(smem_u32(sA + so), Ab + (size_t)r * lda + k0 + ckg);
            cp16(smem_u32(sB + so), Bb + (size_t)r * ldb + k0 + ckg);
        }
        cp_commit();
    };

    float acc[4][8][4];
    #pragma unroll
    for (int i = 0; i < 4; i++)
        #pragma unroll
        for (int j = 0; j < 8; j++)
            #pragma unroll
            for (int q = 0; q < 4; q++)
                acc[i][j][q] = 0.f;

    const int NC = K / KCH;

    #pragma unroll
    for (int s = 0; s < STAGES - 1; s++) issue(s, s);

    for (int ct = 0; ct < NC; ct++) {
        cp_wait<STAGES - 2>();
        __syncthreads();

        if (ct + STAGES - 1 < NC)
            issue(ct + STAGES - 1, (ct + STAGES - 1) & (STAGES - 1));

        const float* sA = sm + (ct & (STAGES - 1)) * STAGE_FLOATS;
        const float* sB = sA + PLANE_FLOATS;

        const bool three = (ct < SPLIT_CHUNKS);

        uint32_t bh[8][2], bl[8][2];
        #pragma unroll
        for (int j = 0; j < 8; j++) {
            const int n = wn + j * 8 + grp;
            float2 q0 = *(const float2*)&sB[n * ROWSTRIDE + 2 * qk];
            float2 q1 = *(const float2*)&sB[n * ROWSTRIDE + 2 * qk + 8];
            if (three) {
                split3(q0.x, q0.y, bh[j][0], bl[j][0]);
                split3(q1.x, q1.y, bh[j][1], bl[j][1]);
            } else {
                bh[j][0] = pack1(q0.x, q0.y);
                bh[j][1] = pack1(q1.x, q1.y);
            }
        }
        #pragma unroll
        for (int i = 0; i < 4; i++) {
            const int r = wm + i * 16 + grp;
            float2 a0 = *(const float2*)&sA[r * ROWSTRIDE + 2 * qk];
            float2 a1 = *(const float2*)&sA[(r + 8) * ROWSTRIDE + 2 * qk];
            float2 a2 = *(const float2*)&sA[r * ROWSTRIDE + 2 * qk + 8];
            float2 a3 = *(const float2*)&sA[(r + 8) * ROWSTRIDE + 2 * qk + 8];
            uint32_t ah[4], al[4];
            if (three) {
                split3(a0.x, a0.y, ah[0], al[0]);
                split3(a1.x, a1.y, ah[1], al[1]);
                split3(a2.x, a2.y, ah[2], al[2]);
                split3(a3.x, a3.y, ah[3], al[3]);
            } else {
                ah[0] = pack1(a0.x, a0.y);
                ah[1] = pack1(a1.x, a1.y);
                ah[2] = pack1(a2.x, a2.y);
                ah[3] = pack1(a3.x, a3.y);
            }
            #pragma unroll
            for (int j = 0; j < 8; j++) mma_bf16(acc[i][j], ah, bh[j]);
            if (three) {
                #pragma unroll
                for (int j = 0; j < 8; j++) mma_bf16(acc[i][j], ah, bl[j]);
                #pragma unroll
                for (int j = 0; j < 8; j++) mma_bf16(acc[i][j], al, bh[j]);
            }
        }
    }

    #pragma unroll
    for (int i = 0; i < 4; i++) {
        const int r = by * 128 + wm + i * 16 + grp;
        #pragma unroll
        for (int j = 0; j < 8; j++) {
            const int c = bx * 128 + wn + j * 8 + qk * 2;
            size_t p0 = (size_t)r * ldc + c;
            size_t p1 = (size_t)(r + 8) * ldc + c;
            float2 o0 = { acc[i][j][0], acc[i][j][1] };
            float2 o1 = { acc[i][j][2], acc[i][j][3] };
            *(float2*)(C + p0) = o0;
            *(float2*)(C + p1) = o1;
        }
    }
}

// ---------------------------------------------------------------------------
extern "C" void kernel_launch(void* const* d_in, const int* in_sizes, int n_in,
                              void* d_out, int out_size)
{
    const float* A   = (const float*)d_in[0];   // (2048, 2048)
    const float* A_F = (const float*)d_in[1];   // (2048, 2048)
    const float* Cm  = (const float*)d_in[2];   // (512, 2048)
    const float* C_F = (const float*)d_in[3];   // (512, 2048)
    float* out = (float*)d_out;

    float* base = nullptr;
    cudaGetSymbolAddress((void**)&base, g_buf);
    cudaFuncSetAttribute(gemm_gd<3>, cudaFuncAttributeMaxDynamicSharedMemorySize,
                         SMEM_DYN);
    cudaFuncSetAttribute(gemm_gd<1>, cudaFuncAttributeMaxDynamicSharedMemorySize,
                         SMEM_DYN);
    cudaFuncSetAttribute(gemm_f, cudaFuncAttributeMaxDynamicSharedMemorySize,
                         SMEM_DYN);

    float* Us = base;                      // 5 slices (2560 x 2048)
    float* Vs = Us + (size_t)5 * SL;
    float* Uc = Vs + (size_t)5 * SL;       // 2048 x 2560
    float* Vc = Uc + (size_t)5 * SL;
    float* M  = Vc + (size_t)5 * SL;       // A_F^T
    float* At = M  + FULL;                 // A^T

    dim3 tb(32, 8);

    // M = A_F^T, At = A^T
    transpose_g<<<dim3(64, 64, 2), tb>>>(A_F, M, A, At, NDIM, NDIM, NDIM, NDIM);

    // slice 0: Us_0 = C_F, Vs_0 = Cm
    cudaMemcpyAsync(Us, C_F, SL * sizeof(float), cudaMemcpyDeviceToDevice);
    cudaMemcpyAsync(Vs, Cm,  SL * sizeof(float), cudaMemcpyDeviceToDevice);

    dim3 gch(16, 4, 2);   // N=2048 (16 x 128), M=512 (4 x 128), dual

    // Step 1 [3-split]: Us_1 = Us_0 @ M^T, Vs_1 = Vs_0 @ A
    gemm_gd<3><<<gch, 128, SMEM_DYN>>>(C_F, M, Us + SL, Cm, At, Vs + SL, NDIM);

    // Steps 2..4 [1-split]
    for (int j = 2; j <= 4; j++) {
        gemm_gd<1><<<gch, 128, SMEM_DYN>>>(
            Us + (size_t)(j - 1) * SL, M,  Us + (size_t)j * SL,
            Vs + (size_t)(j - 1) * SL, At, Vs + (size_t)j * SL, NDIM);
    }

    // Dual transpose: Uc = Us^T (2048 x 2560), Vc = Vs^T
    transpose_g<<<dim3(64, 80, 2), tb>>>(Us, Uc, Vs, Vc, KC3, NDIM, NDIM, KC3);

    // out = Uc @ Vc^T, mixed precision (k<1024 3-split, rest 1-split)
    gemm_f<<<dim3(16, 16, 1), 128, SMEM_DYN>>>(Uc, Vc, out, KC3, KC3, KC3, NDIM);
}

// round 16
// speedup vs baseline: 1.1097x; 1.1097x over previous
#include <cuda_runtime.h>
#include <cuda_bf16.h>
#include <cstdint>

// ---------------------------------------------------------------------------
// Stein solver, low-rank factored truncated series, row-form factor chains.
//   S_N = sum_{j<N} M^j R A^j,  M = A_F^T,  R = C_F^T Cm (rank 512).
//   Ut_{j+1} = Ut_j @ M^T (Bt = M),  V_{j+1} = V_j @ A (Bt = At).
// Truncation at t5 (validated R7-R15).
// Chain step 1: R12's proven 3-split kernel (fp32 operands).
// Chain steps 2-4: 1-split with PRECONVERTED bf16 B-operand (Mb/Atb) --
//   bit-identical rounding moved from per-use pack1 to one-time cvt; B smem
//   halves -> 3-stage/60KB -> 3 CTAs/SM (12 warps/SM).
// Final: one mixed-precision GEMM over K=2560 (k<1024 3-split, rest 1-split).
// ---------------------------------------------------------------------------

#define NDIM 2048
#define PDIM 512
#define FULL ((size_t)NDIM * NDIM)
#define SL   ((size_t)PDIM * NDIM)          /* one 512x2048 slice */
#define KC3  2560                           /* concat K = 5 * 512 */

// Us(5SL) Vs(5SL) Uc(5SL) Vc(5SL) M(4SL) At(4SL)
__device__ float g_buf[(size_t)28 * SL];
__device__ __nv_bfloat16 g_bbuf[(size_t)2 * FULL];   // Mb, Atb

// ---------------------------------------------------------------------------
__device__ __forceinline__ uint32_t smem_u32(const void* p) {
    uint32_t a;
    asm("{ .reg .u64 t; cvta.to.shared.u64 t, %1; cvt.u32.u64 %0, t; }"
        : "=r"(a) : "l"(p));
    return a;
}

__device__ __forceinline__ void cp16(uint32_t saddr, const void* g) {
    asm volatile("cp.async.cg.shared.global [%0], [%1], 16;"
                 :: "r"(saddr), "l"(g));
}

__device__ __forceinline__ void cp_commit() {
    asm volatile("cp.async.commit_group;");
}

template <int N>
__device__ __forceinline__ void cp_wait() {
    asm volatile("cp.async.wait_group %0;" :: "n"(N));
}

__device__ __forceinline__ void split3(float f0, float f1,
                                       uint32_t& hi, uint32_t& lo) {
    uint32_t u0 = __float_as_uint(f0) & 0xffff0000u;
    uint32_t u1 = __float_as_uint(f1) & 0xffff0000u;
    hi = u1 | (u0 >> 16);
    float r0 = f0 - __uint_as_float(u0);
    float r1 = f1 - __uint_as_float(u1);
    asm("cvt.rn.bf16x2.f32 %0, %1, %2;" : "=r"(lo) : "f"(r1), "f"(r0));
}

__device__ __forceinline__ uint32_t pack1(float f0, float f1) {
    uint32_t r;
    asm("cvt.rn.bf16x2.f32 %0, %1, %2;" : "=r"(r) : "f"(f1), "f"(f0));
    return r;
}

__device__ __forceinline__ void mma_bf16(float* d, const uint32_t* a,
                                         const uint32_t* b) {
    asm volatile(
        "mma.sync.aligned.m16n8k16.row.col.f32.bf16.bf16.f32 "
        "{%0,%1,%2,%3}, {%4,%5,%6,%7}, {%8,%9}, {%0,%1,%2,%3};"
        : "+f"(d[0]), "+f"(d[1]), "+f"(d[2]), "+f"(d[3])
        : "r"(a[0]), "r"(a[1]), "r"(a[2]), "r"(a[3]), "r"(b[0]), "r"(b[1]));
}

// ---------------------------------------------------------------------------
// Dual transpose: dst[c*ldd + r] = src[r*lds + c], z selects pair.
// ---------------------------------------------------------------------------
__global__ void transpose_g(const float* __restrict__ s0, float* __restrict__ d0,
                            const float* __restrict__ s1, float* __restrict__ d1,
                            int R, int C, int lds, int ldd)
{
    const float* src = blockIdx.z ? s1 : s0;
    float* dst = blockIdx.z ? d1 : d0;
    __shared__ float tile[32][33];
    int x = blockIdx.x * 32 + threadIdx.x;
    int y = blockIdx.y * 32 + threadIdx.y;
    #pragma unroll
    for (int i = 0; i < 32; i += 8)
        if (y + i < R && x < C)
            tile[threadIdx.y + i][threadIdx.x] = src[(size_t)(y + i) * lds + x];
    __syncthreads();
    x = blockIdx.y * 32 + threadIdx.x;
    y = blockIdx.x * 32 + threadIdx.y;
    #pragma unroll
    for (int i = 0; i < 32; i += 8)
        if (y + i < C && x < R)
            dst[(size_t)(y + i) * ldd + x] = tile[threadIdx.x][threadIdx.y + i];
}

// ---------------------------------------------------------------------------
// Dual transpose writing fp32 AND rn-bf16 copies of the transposed matrix.
// ---------------------------------------------------------------------------
__global__ void transpose_gb(const float* __restrict__ s0, float* __restrict__ d0,
                             __nv_bfloat16* __restrict__ b0,
                             const float* __restrict__ s1, float* __restrict__ d1,
                             __nv_bfloat16* __restrict__ b1)
{
    const float* src = blockIdx.z ? s1 : s0;
    float* dst = blockIdx.z ? d1 : d0;
    __nv_bfloat16* dbf = blockIdx.z ? b1 : b0;
    __shared__ float tile[32][33];
    int x = blockIdx.x * 32 + threadIdx.x;
    int y = blockIdx.y * 32 + threadIdx.y;
    #pragma unroll
    for (int i = 0; i < 32; i += 8)
        tile[threadIdx.y + i][threadIdx.x] = src[(size_t)(y + i) * NDIM + x];
    __syncthreads();
    x = blockIdx.y * 32 + threadIdx.x;
    y = blockIdx.x * 32 + threadIdx.y;
    #pragma unroll
    for (int i = 0; i < 32; i += 8) {
        float v = tile[threadIdx.x][threadIdx.y + i];
        size_t o = (size_t)(y + i) * NDIM + x;
        dst[o] = v;
        dbf[o] = __float2bfloat16(v);
    }
}

// ---------------------------------------------------------------------------
// Step-1 chain GEMM (gemm_n3): R12's proven shape. CTA 64x128, 128 thr
// (4 warps 1x4, warp 64x32), KCH=32, 3-stage ring, stride-40, 2 CTAs/SM.
// ---------------------------------------------------------------------------
#define KCH2 32
#define RS2 40
#define N_PLANE_A (64 * RS2)
#define N_STAGE_FLOATS (N_PLANE_A + 128 * RS2)   /* 7680 */
#define N_SMEM_DYN3 (3 * N_STAGE_FLOATS * 4)     /* 92160 B */

__global__ void __launch_bounds__(128, 2)
gemm_n3(const float* __restrict__ A0, const float* __restrict__ B0,
        float* __restrict__ C0,
        const float* __restrict__ A1, const float* __restrict__ B1,
        float* __restrict__ C1)
{
    extern __shared__ float sm[];

    const float* A = blockIdx.z ? A1 : A0;
    const float* Bt = blockIdx.z ? B1 : B0;
    float* C = blockIdx.z ? C1 : C0;

    const int tid  = threadIdx.x;
    const int wid  = tid >> 5;
    const int lane = tid & 31;
    const int grp  = lane >> 2;
    const int qk   = lane & 3;

    const int bx = blockIdx.x;
    const int by = blockIdx.y;
    const int wn = wid * 32;

    const float* Ab = A  + (size_t)(by * 64) * NDIM;
    const float* Bb = Bt + (size_t)(bx * 128) * NDIM;

    auto issue = [&](int ct, int slot) {
        float* sA = sm + slot * N_STAGE_FLOATS;
        float* sB = sA + N_PLANE_A;
        const int k0 = ct * KCH2;
        #pragma unroll
        for (int p = 0; p < 4; p++) {
            const int g = tid + p * 128;
            const int r = g >> 3;
            const int kg = (g & 7) * 4;
            cp16(smem_u32(sA + (uint32_t)(r * RS2 + kg)),
                 Ab + (size_t)r * NDIM + k0 + kg);
        }
        #pragma unroll
        for (int p = 0; p < 8; p++) {
            const int g = tid + p * 128;
            const int r = g >> 3;
            const int kg = (g & 7) * 4;
            cp16(smem_u32(sB + (uint32_t)(r * RS2 + kg)),
                 Bb + (size_t)r * NDIM + k0 + kg);
        }
        cp_commit();
    };

    float acc[4][4][4];
    #pragma unroll
    for (int i = 0; i < 4; i++)
        #pragma unroll
        for (int j = 0; j < 4; j++)
            #pragma unroll
            for (int q = 0; q < 4; q++)
                acc[i][j][q] = 0.f;

    const int NC = NDIM / KCH2;   // 64

    issue(0, 0);
    issue(1, 1);

    int islot = 2, cslot = 0;
    for (int ct = 0; ct < NC; ct++) {
        cp_wait<1>();
        __syncthreads();

        if (ct + 2 < NC) {
            issue(ct + 2, islot);
            islot = (islot == 2) ? 0 : islot + 1;
        }

        const float* sA = sm + cslot * N_STAGE_FLOATS;
        const float* sB = sA + N_PLANE_A;
        cslot = (cslot == 2) ? 0 : cslot + 1;

        #pragma unroll
        for (int kk = 0; kk < KCH2; kk += 16) {
            uint32_t bh[4][2], bl[4][2];
            #pragma unroll
            for (int j = 0; j < 4; j++) {
                const int n = wn + j * 8 + grp;
                float2 q0 = *(const float2*)&sB[n * RS2 + kk + 2 * qk];
                float2 q1 = *(const float2*)&sB[n * RS2 + kk + 2 * qk + 8];
                split3(q0.x, q0.y, bh[j][0], bl[j][0]);
                split3(q1.x, q1.y, bh[j][1], bl[j][1]);
            }
            #pragma unroll
            for (int i = 0; i < 4; i++) {
                const int r = i * 16 + grp;
                float2 a0 = *(const float2*)&sA[r * RS2 + kk + 2 * qk];
                float2 a1 = *(const float2*)&sA[(r + 8) * RS2 + kk + 2 * qk];
                float2 a2 = *(const float2*)&sA[r * RS2 + kk + 2 * qk + 8];
                float2 a3 = *(const float2*)&sA[(r + 8) * RS2 + kk + 2 * qk + 8];
                uint32_t ah[4], al[4];
                split3(a0.x, a0.y, ah[0], al[0]);
                split3(a1.x, a1.y, ah[1], al[1]);
                split3(a2.x, a2.y, ah[2], al[2]);
                split3(a3.x, a3.y, ah[3], al[3]);
                #pragma unroll
                for (int j = 0; j < 4; j++) mma_bf16(acc[i][j], ah, bh[j]);
                #pragma unroll
                for (int j = 0; j < 4; j++) mma_bf16(acc[i][j], ah, bl[j]);
                #pragma unroll
                for (int j = 0; j < 4; j++) mma_bf16(acc[i][j], al, bh[j]);
            }
        }
    }

    #pragma unroll
    for (int i = 0; i < 4; i++) {
        const int r = by * 64 + i * 16 + grp;
        #pragma unroll
        for (int j = 0; j < 4; j++) {
            const int c = bx * 128 + wn + j * 8 + qk * 2;
            size_t p0 = (size_t)r * NDIM + c;
            size_t p1 = (size_t)(r + 8) * NDIM + c;
            float2 o0 = { acc[i][j][0], acc[i][j][1] };
            float2 o1 = { acc[i][j][2], acc[i][j][3] };
            *(float2*)(C + p0) = o0;
            *(float2*)(C + p1) = o1;
        }
    }
}

// ---------------------------------------------------------------------------
// Chain GEMM steps 2-4 (gemm_nb, 1-split): A fp32, B PRE-CONVERTED bf16.
// Same warp shape as R12 (64x128, 4 warps 1x4, warp 64x32), KCH=32, 3-stage.
// smem/stage: A 64x40 fp32 (10240B) + B 128x40 bf16 (10240B) = 20480B;
// 3 stages = 61440B -> 3 CTAs/SM (12 warps/SM). grid (16, 8, 2).
// B fragment loads: LDS.32 of bf16x2 pairs, word offsets 20g+qk distinct
// mod 32 -> conflict-free. No B-side cvt in mainloop.
// ---------------------------------------------------------------------------
#define NB_STAGE_BYTES (N_PLANE_A * 4 + 128 * RS2 * 2)   /* 20480 */
#define NB_SMEM_DYN (3 * NB_STAGE_BYTES)                 /* 61440 */

__global__ void __launch_bounds__(128, 3)
gemm_nb(const float* __restrict__ A0, const __nv_bfloat16* __restrict__ B0,
        float* __restrict__ C0,
        const float* __restrict__ A1, const __nv_bfloat16* __restrict__ B1,
        float* __restrict__ C1)
{
    extern __shared__ char smc[];

    const float* A = blockIdx.z ? A1 : A0;
    const __nv_bfloat16* Bt = blockIdx.z ? B1 : B0;
    float* C = blockIdx.z ? C1 : C0;

    const int tid  = threadIdx.x;
    const int wid  = tid >> 5;
    const int lane = tid & 31;
    const int grp  = lane >> 2;
    const int qk   = lane & 3;

    const int bx = blockIdx.x;
    const int by = blockIdx.y;
    const int wn = wid * 32;

    const float* Ab = A  + (size_t)(by * 64) * NDIM;
    const __nv_bfloat16* Bb = Bt + (size_t)(bx * 128) * NDIM;

    auto issue = [&](int ct, int slot) {
        char* sA = smc + slot * NB_STAGE_BYTES;            // fp32 plane
        char* sB = sA + N_PLANE_A * 4;                     // bf16 plane
        const int k0 = ct * KCH2;
        // A: 64 rows x 32 fp32 = 512 granules (16B), 4/thread
        #pragma unroll
        for (int p = 0; p < 4; p++) {
            const int g = tid + p * 128;
            const int r = g >> 3;
            const int kg = (g & 7) * 4;
            cp16(smem_u32(sA + (uint32_t)(r * RS2 + kg) * 4),
                 Ab + (size_t)r * NDIM + k0 + kg);
        }
        // B: 128 rows x 32 bf16 = 512 granules (16B = 8 bf16), 4/thread
        #pragma unroll
        for (int p = 0; p < 4; p++) {
            const int g = tid + p * 128;
            const int r = g >> 2;
            const int kg = (g & 3) * 8;
            cp16(smem_u32(sB + (uint32_t)(r * RS2 + kg) * 2),
                 Bb + (size_t)r * NDIM + k0 + kg);
        }
        cp_commit();
    };

    float acc[4][4][4];
    #pragma unroll
    for (int i = 0; i < 4; i++)
        #pragma unroll
        for (int j = 0; j < 4; j++)
            #pragma unroll
            for (int q = 0; q < 4; q++)
                acc[i][j][q] = 0.f;

    const int NC = NDIM / KCH2;   // 64

    issue(0, 0);
    issue(1, 1);

    int islot = 2, cslot = 0;
    for (int ct = 0; ct < NC; ct++) {
        cp_wait<1>();
        __syncthreads();

        if (ct + 2 < NC) {
            issue(ct + 2, islot);
            islot = (islot == 2) ? 0 : islot + 1;
        }

        const char* sAc = smc + cslot * NB_STAGE_BYTES;
        const float* sA = (const float*)sAc;
        const char* sB = sAc + N_PLANE_A * 4;
        cslot = (cslot == 2) ? 0 : cslot + 1;

        #pragma unroll
        for (int kk = 0; kk < KCH2; kk += 16) {
            uint32_t bh[4][2];
            #pragma unroll
            for (int j = 0; j < 4; j++) {
                const int n = wn + j * 8 + grp;
                // bf16x2 pair at k = kk+2qk (and +8): byte off = n*80 + 2k
                bh[j][0] = *(const uint32_t*)(sB + n * (RS2 * 2) + 2 * (kk + 2 * qk));
                bh[j][1] = *(const uint32_t*)(sB + n * (RS2 * 2) + 2 * (kk + 2 * qk + 8));
            }
            #pragma unroll
            for (int i = 0; i < 4; i++) {
                const int r = i * 16 + grp;
                float2 a0 = *(const float2*)&sA[r * RS2 + kk + 2 * qk];
                float2 a1 = *(const float2*)&sA[(r + 8) * RS2 + kk + 2 * qk];
                float2 a2 = *(const float2*)&sA[r * RS2 + kk + 2 * qk + 8];
                float2 a3 = *(const float2*)&sA[(r + 8) * RS2 + kk + 2 * qk + 8];
                uint32_t ah[4];
                ah[0] = pack1(a0.x, a0.y);
                ah[1] = pack1(a1.x, a1.y);
                ah[2] = pack1(a2.x, a2.y);
                ah[3] = pack1(a3.x, a3.y);
                #pragma unroll
                for (int j = 0; j < 4; j++) mma_bf16(acc[i][j], ah, bh[j]);
            }
        }
    }

    #pragma unroll
    for (int i = 0; i < 4; i++) {
        const int r = by * 64 + i * 16 + grp;
        #pragma unroll
        for (int j = 0; j < 4; j++) {
            const int c = bx * 128 + wn + j * 8 + qk * 2;
            size_t p0 = (size_t)r * NDIM + c;
            size_t p1 = (size_t)(r + 8) * NDIM + c;
            float2 o0 = { acc[i][j][0], acc[i][j][1] };
            float2 o1 = { acc[i][j][2], acc[i][j][3] };
            *(float2*)(C + p0) = o0;
            *(float2*)(C + p1) = o1;
        }
    }
}

// ---------------------------------------------------------------------------
// Final GEMM (gemm_f): out = Uc(2048 x 2560) @ Vc^T, mixed precision
// (k < 1024: 3-split; rest: 1-split). CTA 128x128, 128 thr, KCH=16,
// 4-stage, stride-24, 2 CTAs/SM. (R13/R14 verified rel_err-neutral.)
// ---------------------------------------------------------------------------
#define KCH 16
#define ROWSTRIDE 24
#define STAGES 4
#define PLANE_FLOATS (128 * ROWSTRIDE)
#define STAGE_FLOATS (2 * PLANE_FLOATS)
#define SMEM_DYN (STAGES * STAGE_FLOATS * 4)
#define SPLIT_CHUNKS (1024 / KCH)

__global__ void __launch_bounds__(128, 2)
gemm_f(const float* __restrict__ A, const float* __restrict__ Bt,
       float* __restrict__ C, int K, int lda, int ldb, int ldc)
{
    extern __shared__ float sm[];

    const int tid  = threadIdx.x;
    const int wid  = tid >> 5;
    const int lane = tid & 31;
    const int grp  = lane >> 2;
    const int qk   = lane & 3;

    const int bx = blockIdx.x;
    const int by = blockIdx.y;
    const int wm = (wid >> 1) * 64;
    const int wn = (wid & 1) * 64;

    const float* Ab = A  + (size_t)(by * 128) * lda;
    const float* Bb = Bt + (size_t)(bx * 128) * ldb;

    const int crow = tid >> 2;
    const int ckg  = (tid & 3) * 4;

    auto issue = [&](int ct, int slot) {
        float* sA = sm + slot * STAGE_FLOATS;
        float* sB = sA + PLANE_FLOATS;
        const int k0 = ct * KCH;
        #pragma unroll
        for (int p = 0; p < 4; p++) {
            const int r = crow + p * 32;
            const uint32_t so = (uint32_t)(r * ROWSTRIDE + ckg);
            cp16(smem_u32(sA + so), Ab + (size_t)r * lda + k0 + ckg);
            cp16(smem_u32(sB + so), Bb + (size_t)r * ldb + k0 + ckg);
        }
        cp_commit();
    };

    float acc[4][8][4];
    #pragma unroll
    for (int i = 0; i < 4; i++)
        #pragma unroll
        for (int j = 0; j < 8; j++)
            #pragma unroll
            for (int q = 0; q < 4; q++)
                acc[i][j][q] = 0.f;

    const int NC = K / KCH;

    #pragma unroll
    for (int s = 0; s < STAGES - 1; s++) issue(s, s);

    for (int ct = 0; ct < NC; ct++) {
        cp_wait<STAGES - 2>();
        __syncthreads();

        if (ct + STAGES - 1 < NC)
            issue(ct + STAGES - 1, (ct + STAGES - 1) & (STAGES - 1));

        const float* sA = sm + (ct & (STAGES - 1)) * STAGE_FLOATS;
        const float* sB = sA + PLANE_FLOATS;

        const bool three = (ct < SPLIT_CHUNKS);

        uint32_t bh[8][2], bl[8][2];
        #pragma unroll
        for (int j = 0; j < 8; j++) {
            const int n = wn + j * 8 + grp;
            float2 q0 = *(const float2*)&sB[n * ROWSTRIDE + 2 * qk];
            float2 q1 = *(const float2*)&sB[n * ROWSTRIDE + 2 * qk + 8];
            if (three) {
                split3(q0.x, q0.y, bh[j][0], bl[j][0]);
                split3(q1.x, q1.y, bh[j][1], bl[j][1]);
            } else {
                bh[j][0] = pack1(q0.x, q0.y);
                bh[j][1] = pack1(q1.x, q1.y);
            }
        }
        #pragma unroll
        for (int i = 0; i < 4; i++) {
            const int r = wm + i * 16 + grp;
            float2 a0 = *(const float2*)&sA[r * ROWSTRIDE + 2 * qk];
            float2 a1 = *(const float2*)&sA[(r + 8) * ROWSTRIDE + 2 * qk];
            float2 a2 = *(const float2*)&sA[r * ROWSTRIDE + 2 * qk + 8];
            float2 a3 = *(const float2*)&sA[(r + 8) * ROWSTRIDE + 2 * qk + 8];
            uint32_t ah[4], al[4];
            if (three) {
                split3(a0.x, a0.y, ah[0], al[0]);
                split3(a1.x, a1.y, ah[1], al[1]);
                split3(a2.x, a2.y, ah[2], al[2]);
                split3(a3.x, a3.y, ah[3], al[3]);
            } else {
                ah[0] = pack1(a0.x, a0.y);
                ah[1] = pack1(a1.x, a1.y);
                ah[2] = pack1(a2.x, a2.y);
                ah[3] = pack1(a3.x, a3.y);
            }
            #pragma unroll
            for (int j = 0; j < 8; j++) mma_bf16(acc[i][j], ah, bh[j]);
            if (three) {
                #pragma unroll
                for (int j = 0; j < 8; j++) mma_bf16(acc[i][j], ah, bl[j]);
                #pragma unroll
                for (int j = 0; j < 8; j++) mma_bf16(acc[i][j], al, bh[j]);
            }
        }
    }

    #pragma unroll
    for (int i = 0; i < 4; i++) {
        const int r = by * 128 + wm + i * 16 + grp;
        #pragma unroll
        for (int j = 0; j < 8; j++) {
            const int c = bx * 128 + wn + j * 8 + qk * 2;
            size_t p0 = (size_t)r * ldc + c;
            size_t p1 = (size_t)(r + 8) * ldc + c;
            float2 o0 = { acc[i][j][0], acc[i][j][1] };
            float2 o1 = { acc[i][j][2], acc[i][j][3] };
            *(float2*)(C + p0) = o0;
            *(float2*)(C + p1) = o1;
        }
    }
}

// ---------------------------------------------------------------------------
extern "C" void kernel_launch(void* const* d_in, const int* in_sizes, int n_in,
                              void* d_out, int out_size)
{
    const float* A   = (const float*)d_in[0];   // (2048, 2048)
    const float* A_F = (const float*)d_in[1];   // (2048, 2048)
    const float* Cm  = (const float*)d_in[2];   // (512, 2048)
    const float* C_F = (const float*)d_in[3];   // (512, 2048)
    float* out = (float*)d_out;

    float* base = nullptr;
    cudaGetSymbolAddress((void**)&base, g_buf);
    __nv_bfloat16* bbase = nullptr;
    cudaGetSymbolAddress((void**)&bbase, g_bbuf);

    cudaFuncSetAttribute(gemm_n3, cudaFuncAttributeMaxDynamicSharedMemorySize,
                         N_SMEM_DYN3);
    cudaFuncSetAttribute(gemm_nb, cudaFuncAttributeMaxDynamicSharedMemorySize,
                         NB_SMEM_DYN);
    cudaFuncSetAttribute(gemm_f, cudaFuncAttributeMaxDynamicSharedMemorySize,
                         SMEM_DYN);

    float* Us = base;                      // 5 slices (2560 x 2048)
    float* Vs = Us + (size_t)5 * SL;
    float* Uc = Vs + (size_t)5 * SL;       // 2048 x 2560
    float* Vc = Uc + (size_t)5 * SL;
    float* M  = Vc + (size_t)5 * SL;       // A_F^T (fp32)
    float* At = M  + FULL;                 // A^T (fp32)
    __nv_bfloat16* Mb  = bbase;            // bf16 copies
    __nv_bfloat16* Atb = bbase + FULL;

    dim3 tb(32, 8);

    // M = A_F^T (+ bf16 copy), At = A^T (+ bf16 copy)
    transpose_gb<<<dim3(64, 64, 2), tb>>>(A_F, M, Mb, A, At, Atb);

    // slice 0: Us_0 = C_F, Vs_0 = Cm
    cudaMemcpyAsync(Us, C_F, SL * sizeof(float), cudaMemcpyDeviceToDevice);
    cudaMemcpyAsync(Vs, Cm,  SL * sizeof(float), cudaMemcpyDeviceToDevice);

    // Step 1 [3-split, fp32 operands]
    gemm_n3<<<dim3(16, 8, 2), 128, N_SMEM_DYN3>>>(C_F, M, Us + SL,
                                                  Cm, At, Vs + SL);

    // Steps 2..4 [1-split, bf16 B-operand, 3 CTAs/SM]
    for (int j = 2; j <= 4; j++) {
        gemm_nb<<<dim3(16, 8, 2), 128, NB_SMEM_DYN>>>(
            Us + (size_t)(j - 1) * SL, Mb,  Us + (size_t)j * SL,
            Vs + (size_t)(j - 1) * SL, Atb, Vs + (size_t)j * SL);
    }

    // Dual transpose: Uc = Us^T (2048 x 2560), Vc = Vs^T
    transpose_g<<<dim3(64, 80, 2), tb>>>(Us, Uc, Vs, Vc, KC3, NDIM, NDIM, KC3);

    // out = Uc @ Vc^T, mixed precision (k<1024 3-split, rest 1-split)
    gemm_f<<<dim3(16, 16, 1), 128, SMEM_DYN>>>(Uc, Vc, out, KC3, KC3, KC3, NDIM);
}